// round 5
// baseline (speedup 1.0000x reference)
#include <cuda_runtime.h>
#include <cuda_bf16.h>

#define BATCH 256
#define SDIM  1024
#define NOFF  36
#define FP_SCALE 131072.0f      // 2^17

// Packed accumulator: [63:54] warp arrivals, [53:14] fixed-point sum, [13:0] count.
__device__ unsigned long long gPack;   // zero-initialized; reset by last warp each call

__global__ __launch_bounds__(32, 32)
void loss_39934605918651_kernel(const float* __restrict__ y_predict,
                                const int*   __restrict__ gt_pos,
                                float*       __restrict__ out) {
    const int lane = threadIdx.x;
    const int b    = blockIdx.x;

    // ---- Critical path, hop 1: own gt position (same addr warp-wide -> broadcast, 1 wavefront).
    const int2 own = __ldg(&((const int2*)gt_pos)[b]);
    const int  gx  = own.x;
    const int  gy  = own.y;

    // ---- Off-path: moment loads (feed sq only, consumed after the gather returns).
    const int2* g2 = (const int2*)gt_pos;
    int2 p[8];
    #pragma unroll
    for (int k = 0; k < 8; k++) p[k] = __ldg(&g2[lane + 32 * k]);

    // ---- Critical path, hop 2: the gather (addresses depend only on `own`).
    float yh[2];
    int   pxv[2], pyv[2];
    bool  vld[2];
    #pragma unroll
    for (int u = 0; u < 2; u++) {
        const int i  = lane + 32 * u;
        const int q  = i / 6;
        const int oi = q - 3;
        const int oj = i - q * 6 - 3;
        const int px = gx + oi;
        const int py = gy + oj;
        pxv[u] = px; pyv[u] = py;
        vld[u] = (i < NOFF) & (px >= 0) & (px < SDIM) & (py >= 0) & (py < SDIM);
        const int pcx = min(max(px, 0), SDIM - 1);
        const int pcy = min(max(py, 0), SDIM - 1);
        yh[u] = 0.5f;
        if (i < NOFF)
            yh[u] = __ldg(&y_predict[((size_t)b << 20) + ((size_t)pcx << 10) + pcy]);
    }

    // ---- Overlaps gather latency: moment partials + warp REDUX.
    int sx = 0, sy = 0, scc = 0;
    #pragma unroll
    for (int k = 0; k < 8; k++) {
        sx  += p[k].x;
        sy  += p[k].y;
        scc += p[k].x * p[k].x + p[k].y * p[k].y;
    }
    const int Sx = __reduce_add_sync(0xFFFFFFFFu, sx);
    const int Sy = __reduce_add_sync(0xFFFFFFFFu, sy);
    const int Sc = __reduce_add_sync(0xFFFFFFFFu, scc);

    // Closed-form valid count: in-bounds rows x cols of the 6x6 window.
    const int rows = min(gx + 2, SDIM - 1) - max(gx - 3, 0) + 1;
    const int cols = min(gy + 2, SDIM - 1) - max(gy - 3, 0) + 1;
    const int cnt  = rows * cols;

    int fpsum = 0;
    #pragma unroll
    for (int u = 0; u < 2; u++) {
        const int px = pxv[u], py = pyv[u];
        // sq = B*(px^2+py^2) - 2*(px*Sx + py*Sy) + Sc, exact in int32.
        const int   sq_i = BATCH * (px * px + py * py) - 2 * (px * Sx + py * Sy) + Sc;
        const float sq   = (float)sq_i;
        const float y    = __expf(-sq * 0.2f);   // underflows to 0 exactly like fp32 ref
        const float d    = yh[u] - y;
        float term;
        if (y == 1.0f) {
            term = -__logf(yh[u]) * d * d;
        } else {
            const float omy = 1.0f - y;
            const float w2  = omy * omy;
            term = -__logf(1.0f - yh[u]) * (w2 * w2) * d * d;
        }
        if (vld[u]) fpsum += __float2int_rn(term * FP_SCALE);   // term >= 0
    }

    // Single exact warp reduction.
    fpsum = __reduce_add_sync(0xFFFFFFFFu, fpsum);

    if (lane == 0) {
        const unsigned long long mine =
            (1ULL << 54) | ((unsigned long long)(unsigned int)fpsum << 14)
                         | (unsigned long long)cnt;
        const unsigned long long old = atomicAdd(&gPack, mine);
        if ((old >> 54) == (unsigned long long)(BATCH - 1)) {
            const unsigned long long tot = old + mine;   // complete total, no readback
            const long long fp = (long long)((tot >> 14) & ((1ULL << 40) - 1));
            const int       c  = (int)(tot & 0x3FFFULL);
            out[0] = (float)(((double)fp / (double)FP_SCALE) / (double)c);
            atomicExch(&gPack, 0ULL);                    // reset for next graph replay
        }
    }
}

extern "C" void kernel_launch(void* const* d_in, const int* in_sizes, int n_in,
                              void* d_out, int out_size) {
    const float* y_predict = (const float*)d_in[0];
    const int*   gt_pos    = (const int*)d_in[1];
    float*       out       = (float*)d_out;
    loss_39934605918651_kernel<<<BATCH, 32>>>(y_predict, gt_pos, out);
}

// round 6
// speedup vs baseline: 1.3527x; 1.3527x over previous
#include <cuda_runtime.h>
#include <cuda_bf16.h>

#define BATCH 256
#define SDIM  1024
#define NOFF  36
#define FP_SCALE 131072.0f      // 2^17

// Packed accumulator: [63:54] CTA arrivals, [53:14] fixed-point sum, [13:0] count.
__device__ unsigned long long gPack;   // zero-initialized; reset by last CTA each call

__global__ __launch_bounds__(32, 32)
void loss_39934605918651_kernel(const float* __restrict__ y_predict,
                                const int*   __restrict__ gt_pos,
                                float*       __restrict__ out) {
    const int b = blockIdx.x;
    const int t = threadIdx.x;

    // Each lane loads 8 gt pairs -> warp covers all 256 batches.
    const int2* g2 = (const int2*)gt_pos;
    int2 p[8];
    #pragma unroll
    for (int k = 0; k < 8; k++) p[k] = __ldg(&g2[t + 32 * k]);

    // Moment partials.
    int sx = 0, sy = 0, scc = 0;
    #pragma unroll
    for (int k = 0; k < 8; k++) {
        sx  += p[k].x;
        sy  += p[k].y;
        scc += p[k].x * p[k].x + p[k].y * p[k].y;
    }

    // This CTA's own gt position: predicated select of reg k = b>>5, then shuffle from lane b&31.
    const int kown = b >> 5;
    int gxl = p[0].x, gyl = p[0].y;
    #pragma unroll
    for (int k = 1; k < 8; k++) {
        if (kown == k) { gxl = p[k].x; gyl = p[k].y; }
    }
    const int gx = __shfl_sync(0xFFFFFFFFu, gxl, b & 31);
    const int gy = __shfl_sync(0xFFFFFFFFu, gyl, b & 31);

    // Warp-wide exact moment sums (single REDUX each).
    const int Sx = __reduce_add_sync(0xFFFFFFFFu, sx);
    const int Sy = __reduce_add_sync(0xFFFFFFFFu, sy);
    const int Sc = __reduce_add_sync(0xFFFFFFFFu, scc);

    // Closed-form valid count: in-bounds rows x cols of the 6x6 window.
    const int rows = min(gx + 2, SDIM - 1) - max(gx - 3, 0) + 1;
    const int cols = min(gy + 2, SDIM - 1) - max(gy - 3, 0) + 1;
    const int cnt  = rows * cols;

    int fpsum = 0;

    #pragma unroll
    for (int i = t; i < NOFF; i += 32) {
        const int q  = i / 6;
        const int oi = q - 3;
        const int oj = i - q * 6 - 3;
        const int px = gx + oi;
        const int py = gy + oj;

        const bool valid = (px >= 0) & (px < SDIM) & (py >= 0) & (py < SDIM);
        const int pcx = min(max(px, 0), SDIM - 1);
        const int pcy = min(max(py, 0), SDIM - 1);

        const float y_hat = __ldg(&y_predict[((size_t)b << 20) + ((size_t)pcx << 10) + pcy]);

        // sq = B*(px^2+py^2) - 2*(px*Sx + py*Sy) + Sc, exact in int32.
        const int   sq_i = BATCH * (px * px + py * py) - 2 * (px * Sx + py * Sy) + Sc;
        const float sq   = (float)sq_i;
        const float y    = __expf(-sq * 0.2f);   // underflows to 0 exactly like fp32 ref
        const float d    = y_hat - y;
        float term;
        if (y == 1.0f) {
            term = -__logf(y_hat) * d * d;
        } else {
            const float omy = 1.0f - y;
            const float w2  = omy * omy;
            term = -__logf(1.0f - y_hat) * (w2 * w2) * d * d;
        }
        if (valid) fpsum += __float2int_rn(term * FP_SCALE);   // term >= 0
    }

    // Exact, order-independent warp reduction.
    fpsum = __reduce_add_sync(0xFFFFFFFFu, fpsum);

    if (t == 0) {
        const unsigned long long mine =
            (1ULL << 54) | ((unsigned long long)(unsigned int)fpsum << 14)
                         | (unsigned long long)cnt;
        const unsigned long long old = atomicAdd(&gPack, mine);
        if ((old >> 54) == (unsigned long long)(BATCH - 1)) {
            const unsigned long long tot = old + mine;   // complete total, no readback
            const long long fp = (long long)((tot >> 14) & ((1ULL << 40) - 1));
            const int       c  = (int)(tot & 0x3FFFULL);
            out[0] = (float)(((double)fp / (double)FP_SCALE) / (double)c);
            atomicExch(&gPack, 0ULL);                    // reset for next graph replay
        }
    }
}

extern "C" void kernel_launch(void* const* d_in, const int* in_sizes, int n_in,
                              void* d_out, int out_size) {
    const float* y_predict = (const float*)d_in[0];
    const int*   gt_pos    = (const int*)d_in[1];
    float*       out       = (float*)d_out;
    loss_39934605918651_kernel<<<BATCH, 32>>>(y_predict, gt_pos, out);
}